// round 9
// baseline (speedup 1.0000x reference)
#include <cuda_runtime.h>
#include <math.h>
#include <stdint.h>

// ---------------- problem constants ----------------
#define BB    256
#define CDDN  5
#define HISN  50
#define TT    20
#define DD    300
#define HH    16
#define VDIM  16
#define RPR   256
#define QDQ   200
#define NITEMS (BB*(CDDN+HISN))
#define SCALE 0.05773502691896258f   // 1/sqrt(300), both levels

// ---------------- device scratch ----------------
__device__ float g_cdd[BB*CDDN*RPR];
__device__ float g_his[BB*HISN*RPR];
__device__ float g_nval[BB*HISN*RPR];
__device__ float g_user[BB*RPR];

// ---------------- packed f32x2 helpers ----------------
__device__ __forceinline__ uint64_t pk2(float a, float b){
    uint64_t r; asm("mov.b64 %0,{%1,%2};" : "=l"(r) : "f"(a), "f"(b)); return r;
}
__device__ __forceinline__ void fma2(uint64_t& d, uint64_t a, uint64_t b){
    asm("fma.rn.f32x2 %0,%1,%2,%0;" : "+l"(d) : "l"(a), "l"(b));
}
__device__ __forceinline__ float2 up2(uint64_t v){
    float2 f; asm("mov.b64 {%0,%1},%2;" : "=f"(f.x), "=f"(f.y) : "l"(v)); return f;
}

extern __shared__ float sm[];

// ================= word-level encoder: one CTA (640 thr) per ITEM PAIR =================
// smem (floats):
//   xT  : 2 items x [300][24]            @ 0      (14400)
//   qT  : 4 planes(it,hl) x [300][21]    @ 14400  (25200)
//   Vh  : 4 planes x [20][16]            @ 39600  (1280)
//   val : 2 items x [20][256]            @ 40880  (10240)
//   attn: 4 planes x [20][21]            @ 51120  (1680)
//   wl  : 2 x 20                         @ 52800  (40)
#define W_XT_OFF   0
#define W_QT_OFF   14400
#define W_VH_OFF   39600
#define W_VAL_OFF  40880
#define W_ATT_OFF  51120
#define W_WL_OFF   52800
#define W_SMEM_FLOATS 52840            // 211,360 B (~206.4 KB)

__global__ __launch_bounds__(640, 1)
void word_kernel(const int* __restrict__ cand, const int* __restrict__ clicked,
                 const float* __restrict__ emb,
                 const float* __restrict__ Wq, const float* __restrict__ Wv,
                 const float* __restrict__ Wk, const float* __restrict__ bk,
                 const float* __restrict__ qv)
{
    float* xT   = sm + W_XT_OFF;
    float* qT   = sm + W_QT_OFF;
    float* Vh   = sm + W_VH_OFF;
    float* val  = sm + W_VAL_OFF;
    float* attn = sm + W_ATT_OFF;
    float* wl   = sm + W_WL_OFF;
    __shared__ int tok[2*TT];

    const int tid = threadIdx.x;
    const int bid = blockIdx.x;

    // token load for both items
    if (tid < 2*TT) {
        int it = tid / TT, s = tid % TT;
        int gi = 2*bid + it;
        const int* tp = (gi < BB*CDDN) ? (cand + gi*TT)
                                       : (clicked + (gi - BB*CDDN)*TT);
        tok[it*TT + s] = tp[s];
    }
    __syncthreads();

    // gather x transposed, both items
    for (int p = tid; p < 2*TT*DD; p += 640) {
        int it = p / (TT*DD), r = p % (TT*DD);
        int s = r / DD, f = r - s*DD;
        xT[it*7200 + f*24 + s] = emb[tok[it*TT + s]*DD + f];
    }
    __syncthreads();

    // ======== 8 iterations of 2 heads ========
    for (int g = 0; g < 8; g++) {
        // ---- Q: 600 threads = 2 heads x 300 cols; each thread serves BOTH
        //      items from one loaded weight (reuse in registers) ----
        if (tid < 600) {
            const int hl  = tid / 300;
            const int col = tid % 300;
            const int h   = 2*g + hl;
            const float* wq = Wq + (size_t)h*(DD*DD) + col;
            uint64_t a0[10], a1[10];
            #pragma unroll
            for (int k = 0; k < 10; k++) { a0[k] = 0ull; a1[k] = 0ull; }
            float w0 = wq[0];
            float w1 = wq[DD];
            #pragma unroll 1
            for (int f = 0; f < DD; f++) {
                int fn = (f + 2 < DD) ? (f + 2) : 0;
                float wn = wq[fn*DD];
                uint64_t pw = pk2(w0, w0);
                {
                    const ulonglong2* xr = (const ulonglong2*)(xT + f*24);
                    ulonglong2 x0 = xr[0], x1 = xr[1], x2 = xr[2], x3 = xr[3], x4 = xr[4];
                    fma2(a0[0], x0.x, pw); fma2(a0[1], x0.y, pw);
                    fma2(a0[2], x1.x, pw); fma2(a0[3], x1.y, pw);
                    fma2(a0[4], x2.x, pw); fma2(a0[5], x2.y, pw);
                    fma2(a0[6], x3.x, pw); fma2(a0[7], x3.y, pw);
                    fma2(a0[8], x4.x, pw); fma2(a0[9], x4.y, pw);
                }
                {
                    const ulonglong2* xr = (const ulonglong2*)(xT + 7200 + f*24);
                    ulonglong2 x0 = xr[0], x1 = xr[1], x2 = xr[2], x3 = xr[3], x4 = xr[4];
                    fma2(a1[0], x0.x, pw); fma2(a1[1], x0.y, pw);
                    fma2(a1[2], x1.x, pw); fma2(a1[3], x1.y, pw);
                    fma2(a1[4], x2.x, pw); fma2(a1[5], x2.y, pw);
                    fma2(a1[6], x3.x, pw); fma2(a1[7], x3.y, pw);
                    fma2(a1[8], x4.x, pw); fma2(a1[9], x4.y, pw);
                }
                w0 = w1; w1 = wn;
            }
            float* qA = qT + hl*6300 + col*21;          // item 0 plane
            float* qB = qA + 2*6300;                    // item 1 plane
            #pragma unroll
            for (int k = 0; k < 10; k++) {
                float2 a = up2(a0[k]); qA[2*k] = a.x; qA[2*k+1] = a.y;
                float2 b = up2(a1[k]); qB[2*k] = b.x; qB[2*k+1] = b.y;
            }
        }

        // ---- Vh = x @ Wv_h for the 2 heads, both items (320 jobs) ----
        if (tid < 320) {
            int pl = tid / 80, r = tid % 80, s = r >> 2, vq = r & 3;
            int it = pl >> 1, hl = pl & 1, h = 2*g + hl;
            const float* w = Wv + h*(DD*VDIM) + vq*4;
            const float* xb = xT + it*7200;
            uint64_t c0 = 0, c1 = 0;
            #pragma unroll 4
            for (int f = 0; f < DD; f++) {
                float xv = xb[f*24 + s];
                uint64_t px = pk2(xv, xv);
                ulonglong2 wv = *(const ulonglong2*)(w + f*VDIM);
                fma2(c0, px, wv.x); fma2(c1, px, wv.y);
            }
            float2 r0 = up2(c0), r1 = up2(c1);
            *(float4*)(Vh + pl*320 + s*16 + vq*4) = make_float4(r0.x, r0.y, r1.x, r1.y);
        }
        __syncthreads();

        // ---- logits: 4 planes x 20 s x 5 u-quads = 400 jobs ----
        if (tid < 400) {
            int pl = tid / 100, r = tid % 100, s = r % 20, uq = r / 20;
            int it = pl >> 1;
            const float* qh = qT + pl*6300;
            const float* xb = xT + it*7200;
            uint64_t c0 = 0, c1 = 0;
            #pragma unroll 4
            for (int e = 0; e < DD; e++) {
                float q = qh[e*21 + s];
                uint64_t pq = pk2(q, q);
                ulonglong2 xv = *(const ulonglong2*)(xb + e*24 + uq*4);
                fma2(c0, pq, xv.x); fma2(c1, pq, xv.y);
            }
            float2 r0 = up2(c0), r1 = up2(c1);
            float* ar = attn + pl*420 + s*21 + uq*4;
            ar[0]=r0.x*SCALE; ar[1]=r0.y*SCALE; ar[2]=r1.x*SCALE; ar[3]=r1.y*SCALE;
        }
        __syncthreads();

        // ---- softmax: 4 planes x 20 rows ----
        if (tid < 80) {
            float* row = attn + (tid/20)*420 + (tid%20)*21;
            float m = row[0];
            #pragma unroll
            for (int u = 1; u < TT; u++) m = fmaxf(m, row[u]);
            float sum = 0.f;
            #pragma unroll
            for (int u = 0; u < TT; u++) { float e = __expf(row[u]-m); row[u]=e; sum+=e; }
            float inv = 1.f/sum;
            #pragma unroll
            for (int u = 0; u < TT; u++) row[u] *= inv;
        }
        __syncthreads();

        // ---- val = attn @ Vh : 4 planes x 320 = 1280 jobs ----
        for (int p = tid; p < 1280; p += 640) {
            int pl = p / 320, rm = p % 320, s = rm >> 4, v = rm & 15;
            int it = pl >> 1, h = 2*g + (pl & 1);
            const float* ar = attn + pl*420 + s*21;
            const float* vb = Vh + pl*320 + v;
            float a = 0.f;
            #pragma unroll
            for (int u = 0; u < TT; u++) a += ar[u] * vb[u*16];
            val[it*5120 + s*RPR + h*VDIM + v] = a;
        }
        __syncthreads();
    }

    // ---- additive pooling, both items: 2000 jobs ----
    if (tid < 2*TT) wl[tid] = 0.f;
    __syncthreads();
    for (int p = tid; p < 2*TT*50; p += 640) {
        int it = p / 1000, r = p % 1000, s = r / 50, kq = r % 50, k = kq*4;
        float4 b4 = *(const float4*)(bk + k);
        uint64_t c0 = pk2(b4.x, b4.y), c1 = pk2(b4.z, b4.w);
        const float* vr  = val + it*5120 + s*RPR;
        const float* wkp = Wk + k;
        #pragma unroll 8
        for (int rr = 0; rr < RPR; rr++) {
            uint64_t pv = pk2(vr[rr], vr[rr]);
            ulonglong2 wv = *(const ulonglong2*)(wkp + rr*QDQ);
            fma2(c0, pv, wv.x); fma2(c1, pv, wv.y);
        }
        float2 r0 = up2(c0), r1 = up2(c1);
        float4 q4 = *(const float4*)(qv + k);
        float ts = tanhf(r0.x)*q4.x + tanhf(r0.y)*q4.y + tanhf(r1.x)*q4.z + tanhf(r1.y)*q4.w;
        atomicAdd(&wl[it*TT + s], ts);
    }
    __syncthreads();
    if (tid < 2) {
        float* w = wl + tid*TT;
        float m = -1e30f;
        for (int s = 0; s < TT; s++) { w[s] *= SCALE; m = fmaxf(m, w[s]); }
        float sum = 0.f;
        for (int s = 0; s < TT; s++) { float e = __expf(w[s]-m); w[s]=e; sum+=e; }
        float inv = 1.f/sum;
        for (int s = 0; s < TT; s++) w[s] *= inv;
    }
    __syncthreads();
    if (tid < 2*RPR) {
        int it = tid >> 8, rc = tid & 255;
        const float* w = wl + it*TT;
        const float* vb = val + it*5120 + rc;
        float a = 0.f;
        #pragma unroll
        for (int s = 0; s < TT; s++) a += w[s] * vb[s*RPR];
        int gi = 2*bid + it;
        float* outp = (gi < BB*CDDN) ? (g_cdd + gi*RPR)
                                     : (g_his + (gi - BB*CDDN)*RPR);
        outp[rc] = a;
    }
}

// ================= news level: (b,h)-parallel attention =================
// smem: xT[256][52] | qT[256][51] | attn[50][51] | Vh[50][16]
#define NA_XP 52
#define NA_QP 51
#define NA_QT_OFF (256*NA_XP)                 // 13312
#define NA_AT_OFF (NA_QT_OFF + 256*NA_QP)     // 26368
#define NA_V_OFF  (NA_AT_OFF + 50*51 + 2)     // 28920  (16B-aligned)
#define NA_SMEM_FLOATS (NA_V_OFF + 50*16)     // 29720 (118.9 KB)

__global__ __launch_bounds__(256, 1)
void news_attn_kernel(const float* __restrict__ Wq, const float* __restrict__ Wv)
{
    float* xT   = sm;
    float* qT   = sm + NA_QT_OFF;
    float* attn = sm + NA_AT_OFF;
    float* Vh   = sm + NA_V_OFF;

    const int tid = threadIdx.x;
    const int h   = blockIdx.x;
    const int b   = blockIdx.y;
    const float* x = g_his + b*HISN*RPR;     // [50][256]

    for (int p = tid; p < HISN*RPR; p += 256) {
        int f = p & 255, s = p >> 8;
        xT[f*NA_XP + s] = x[p];
    }
    for (int p = tid; p < 512; p += 256)       // zero pad cols 50,51
        xT[(p>>1)*NA_XP + 50 + (p&1)] = 0.f;
    __syncthreads();

    // Vh = x @ Wv_h : 50x4 quad jobs, unroll 4
    if (tid < 200) {
        int s = tid >> 2, v = (tid & 3)*4;
        const float* w = Wv + h*(RPR*VDIM) + v;
        uint64_t a0 = 0, a1 = 0;
        #pragma unroll 4
        for (int f = 0; f < RPR; f++) {
            float xv = xT[f*NA_XP + s];
            uint64_t px = pk2(xv, xv);
            ulonglong2 wv = *(const ulonglong2*)(w + f*VDIM);
            fma2(a0, px, wv.x); fma2(a1, px, wv.y);
        }
        float2 r0 = up2(a0), r1 = up2(a1);
        *(float4*)(Vh + s*16 + v) = make_float4(r0.x, r0.y, r1.x, r1.y);
    }

    // Q_h: thread = column tid, 25 s-pairs; software-pipelined Wq prefetch
    {
        uint64_t acc[25];
        #pragma unroll
        for (int k = 0; k < 25; k++) acc[k] = 0ull;
        const float* wq = Wq + (size_t)h*(RPR*RPR) + tid;
        float w0 = wq[0];
        float w1 = wq[RPR];
        #pragma unroll 1
        for (int f = 0; f < RPR; f += 2) {
            int fn = (f + 2 < RPR) ? (f + 2) : 0;
            float n0 = wq[fn*RPR];
            float n1 = wq[(fn+1)*RPR];
            {
                uint64_t pw = pk2(w0, w0);
                const ulonglong2* xr = (const ulonglong2*)(xT + f*NA_XP);
                #pragma unroll
                for (int k = 0; k < 12; k++) {
                    ulonglong2 xv = xr[k];
                    fma2(acc[2*k],   xv.x, pw);
                    fma2(acc[2*k+1], xv.y, pw);
                }
                uint64_t xt = *(const uint64_t*)(xT + f*NA_XP + 48);
                fma2(acc[24], xt, pw);
            }
            {
                uint64_t pw = pk2(w1, w1);
                const ulonglong2* xr = (const ulonglong2*)(xT + (f+1)*NA_XP);
                #pragma unroll
                for (int k = 0; k < 12; k++) {
                    ulonglong2 xv = xr[k];
                    fma2(acc[2*k],   xv.x, pw);
                    fma2(acc[2*k+1], xv.y, pw);
                }
                uint64_t xt = *(const uint64_t*)(xT + (f+1)*NA_XP + 48);
                fma2(acc[24], xt, pw);
            }
            w0 = n0; w1 = n1;
        }
        float* q0 = qT + tid*NA_QP;
        #pragma unroll
        for (int k = 0; k < 25; k++) {
            float2 a = up2(acc[k]); q0[2*k] = a.x; q0[2*k+1] = a.y;
        }
    }
    __syncthreads();

    // logits: u-quads, 50x13 jobs, unroll 4
    for (int p = tid; p < 650; p += 256) {
        int s = p % 50, uq = p / 50, u = uq*4;
        uint64_t a0 = 0, a1 = 0;
        #pragma unroll 4
        for (int e = 0; e < RPR; e++) {
            float q = qT[e*NA_QP + s];
            uint64_t pq = pk2(q, q);
            ulonglong2 xv = *(const ulonglong2*)(xT + e*NA_XP + u);
            fma2(a0, pq, xv.x); fma2(a1, pq, xv.y);
        }
        float2 r0 = up2(a0), r1 = up2(a1);
        float* ar = attn + s*51;
        ar[u] = r0.x*SCALE;
        if (u+1 < 50) ar[u+1] = r0.y*SCALE;
        if (u+2 < 50) { ar[u+2] = r1.x*SCALE; ar[u+3] = r1.y*SCALE; }
    }
    __syncthreads();

    if (tid < 50) {
        float* row = attn + tid*51;
        float m = row[0];
        for (int u = 1; u < 50; u++) m = fmaxf(m, row[u]);
        float sum = 0.f;
        for (int u = 0; u < 50; u++) { float e = __expf(row[u]-m); row[u]=e; sum+=e; }
        float inv = 1.f/sum;
        for (int u = 0; u < 50; u++) row[u] *= inv;
    }
    __syncthreads();

    for (int p = tid; p < 800; p += 256) {
        int s = p >> 4, v = p & 15;
        const float* ar = attn + s*51;
        float a = 0.f;
        #pragma unroll 10
        for (int u = 0; u < 50; u++) a += ar[u]*Vh[u*16 + v];
        g_nval[(b*HISN + s)*RPR + h*VDIM + v] = a;
    }
}

// ================= news pooling =================
#define NP_SMEM_FLOATS (HISN*RPR + HISN)      // 12850 (51.4 KB)

__global__ __launch_bounds__(256, 2)
void news_pool_kernel(const float* __restrict__ Wk, const float* __restrict__ bk,
                      const float* __restrict__ qv)
{
    float* val = sm;
    float* wl  = sm + HISN*RPR;
    const int tid = threadIdx.x;
    const int b   = blockIdx.x;

    for (int p = tid; p < HISN*RPR; p += 256) val[p] = g_nval[b*HISN*RPR + p];
    if (tid < HISN) wl[tid] = 0.f;
    __syncthreads();

    for (int p = tid; p < HISN*50; p += 256) {
        int s = p/50, kq = p%50, k = kq*4;
        float4 b4 = *(const float4*)(bk + k);
        uint64_t a0 = pk2(b4.x, b4.y), a1 = pk2(b4.z, b4.w);
        const float* vr  = val + s*RPR;
        const float* wkp = Wk + k;
        #pragma unroll 8
        for (int r = 0; r < RPR; r++) {
            uint64_t pv = pk2(vr[r], vr[r]);
            ulonglong2 wv = *(const ulonglong2*)(wkp + r*QDQ);
            fma2(a0, pv, wv.x); fma2(a1, pv, wv.y);
        }
        float2 r0 = up2(a0), r1 = up2(a1);
        float4 q4 = *(const float4*)(qv + k);
        float ts = tanhf(r0.x)*q4.x + tanhf(r0.y)*q4.y + tanhf(r1.x)*q4.z + tanhf(r1.y)*q4.w;
        atomicAdd(&wl[s], ts);
    }
    __syncthreads();
    if (tid == 0) {
        float m = -1e30f;
        for (int s = 0; s < HISN; s++) { wl[s] *= SCALE; m = fmaxf(m, wl[s]); }
        float sum = 0.f;
        for (int s = 0; s < HISN; s++) { float e = __expf(wl[s]-m); wl[s]=e; sum+=e; }
        float inv = 1.f/sum;
        for (int s = 0; s < HISN; s++) wl[s] *= inv;
    }
    __syncthreads();
    if (tid < RPR) {
        float a = 0.f;
        #pragma unroll 10
        for (int s = 0; s < HISN; s++) a += wl[s] * val[s*RPR + tid];
        g_user[b*RPR + tid] = a;
    }
}

// ================= scores + log_softmax =================
__global__ void score_kernel(float* __restrict__ out)
{
    __shared__ float sc[CDDN];
    const int b = blockIdx.x;
    const int w = threadIdx.x >> 5, lane = threadIdx.x & 31;
    if (w < CDDN) {
        const float* c = g_cdd + (b*CDDN + w)*RPR;
        const float* u = g_user + b*RPR;
        float a = 0.f;
        #pragma unroll
        for (int k = lane; k < RPR; k += 32) a += c[k]*u[k];
        #pragma unroll
        for (int off = 16; off; off >>= 1) a += __shfl_down_sync(0xffffffffu, a, off);
        if (lane == 0) sc[w] = a;
    }
    __syncthreads();
    if (threadIdx.x == 0) {
        float m = sc[0];
        for (int c = 1; c < CDDN; c++) m = fmaxf(m, sc[c]);
        float sum = 0.f;
        for (int c = 0; c < CDDN; c++) sum += __expf(sc[c]-m);
        float lse = logf(sum) + m;
        for (int c = 0; c < CDDN; c++) out[b*CDDN + c] = sc[c] - lse;
    }
}

// ================= launch =================
extern "C" void kernel_launch(void* const* d_in, const int* in_sizes, int n_in,
                              void* d_out, int out_size)
{
    (void)in_sizes; (void)n_in; (void)out_size;
    const int*   cand    = (const int*)d_in[0];
    const int*   clicked = (const int*)d_in[1];
    const float* emb     = (const float*)d_in[2];
    const float* Wq_w    = (const float*)d_in[3];
    const float* Wv_w    = (const float*)d_in[4];
    const float* Wk_w    = (const float*)d_in[5];
    const float* bk_w    = (const float*)d_in[6];
    const float* q_w     = (const float*)d_in[7];
    const float* Wq_n    = (const float*)d_in[8];
    const float* Wv_n    = (const float*)d_in[9];
    const float* Wk_n    = (const float*)d_in[10];
    const float* bk_n    = (const float*)d_in[11];
    const float* q_n     = (const float*)d_in[12];
    float* out = (float*)d_out;

    const size_t smw  = W_SMEM_FLOATS  * sizeof(float);
    const size_t smna = NA_SMEM_FLOATS * sizeof(float);
    const size_t smnp = NP_SMEM_FLOATS * sizeof(float);
    cudaFuncSetAttribute(word_kernel,      cudaFuncAttributeMaxDynamicSharedMemorySize, (int)smw);
    cudaFuncSetAttribute(news_attn_kernel, cudaFuncAttributeMaxDynamicSharedMemorySize, (int)smna);
    cudaFuncSetAttribute(news_pool_kernel, cudaFuncAttributeMaxDynamicSharedMemorySize, (int)smnp);

    word_kernel<<<NITEMS/2, 640, smw>>>(cand, clicked, emb, Wq_w, Wv_w, Wk_w, bk_w, q_w);
    news_attn_kernel<<<dim3(HH, BB), 256, smna>>>(Wq_n, Wv_n);
    news_pool_kernel<<<BB, 256, smnp>>>(Wk_n, bk_n, q_n);
    score_kernel<<<BB, 192>>>(out);
}

// round 10
// speedup vs baseline: 1.3291x; 1.3291x over previous
#include <cuda_runtime.h>
#include <math.h>
#include <stdint.h>

// ---------------- problem constants ----------------
#define BB    256
#define CDDN  5
#define HISN  50
#define TT    20
#define DD    300
#define HH    16
#define VDIM  16
#define RPR   256
#define QDQ   200
#define NITEMS (BB*(CDDN+HISN))
#define SCALE 0.05773502691896258f   // 1/sqrt(300), both levels

// ---------------- device scratch ----------------
__device__ float g_cdd[BB*CDDN*RPR];
__device__ float g_his[BB*HISN*RPR];
__device__ float g_nval[BB*HISN*RPR];
__device__ float g_user[BB*RPR];

// ---------------- packed f32x2 helpers ----------------
__device__ __forceinline__ uint64_t pk2(float a, float b){
    uint64_t r; asm("mov.b64 %0,{%1,%2};" : "=l"(r) : "f"(a), "f"(b)); return r;
}
__device__ __forceinline__ void fma2(uint64_t& d, uint64_t a, uint64_t b){
    asm("fma.rn.f32x2 %0,%1,%2,%0;" : "+l"(d) : "l"(a), "l"(b));
}
__device__ __forceinline__ float2 up2(uint64_t v){
    float2 f; asm("mov.b64 {%0,%1},%2;" : "=f"(f.x), "=f"(f.y) : "l"(v)); return f;
}
#define GBAR(id) asm volatile("bar.sync %0, 160;" :: "r"(id) : "memory")

extern __shared__ float sm[];

// ================= word-level encoder: one CTA (640 thr) per news item =================
// smem: xT[300][24] | qT[4][300][21] | V[20][256] | val[20][256] | attn[4][20][21] | wl[20]
#define W_XP 24
#define W_QP 21
#define W_QT_OFF  (300*W_XP)                 // 7200
#define W_V_OFF   (W_QT_OFF + 4*300*W_QP)    // 32400
#define W_VAL_OFF (W_V_OFF  + TT*RPR)        // 37520
#define W_ATT_OFF (W_VAL_OFF + TT*RPR)       // 42640
#define W_WL_OFF  (W_ATT_OFF + 4*TT*21)      // 44320
#define W_SMEM_FLOATS (W_WL_OFF + TT)        // 44340  (177.4 KB)

__global__ __launch_bounds__(640, 1)
void word_kernel(const int* __restrict__ cand, const int* __restrict__ clicked,
                 const float* __restrict__ emb,
                 const float* __restrict__ Wq, const float* __restrict__ Wv,
                 const float* __restrict__ Wk, const float* __restrict__ bk,
                 const float* __restrict__ qv)
{
    float* xT   = sm;
    float* qT   = sm + W_QT_OFF;
    float* V    = sm + W_V_OFF;
    float* val  = sm + W_VAL_OFF;
    float* attn = sm + W_ATT_OFF;
    float* wl   = sm + W_WL_OFF;
    __shared__ int tok[TT];

    const int tid  = threadIdx.x;
    const int item = blockIdx.x;

    const int* tp = (item < BB*CDDN) ? (cand + item*TT)
                                     : (clicked + (item - BB*CDDN)*TT);
    if (tid < TT) tok[tid] = tp[tid];
    __syncthreads();

    // gather x transposed
    for (int p = tid; p < TT*DD; p += 640) {
        int s = p / DD, f = p - s*DD;
        xT[f*W_XP + s] = emb[tok[s]*DD + f];
    }
    __syncthreads();

    // ---- V = x @ Wv_all : quad columns, f32x2, MLP-4 on Wv loads ----
    for (int p = tid; p < TT*64; p += 640) {
        int s = p >> 6, cq = p & 63, c = cq*4;
        int h = c >> 4, v = c & 15;
        const float* w = Wv + h*(DD*VDIM) + v;
        uint64_t a0 = 0, a1 = 0;
        #pragma unroll 4
        for (int f = 0; f < DD; f++) {
            float xv = xT[f*W_XP + s];
            uint64_t px = pk2(xv, xv);
            ulonglong2 wv = *(const ulonglong2*)(w + f*VDIM);
            fma2(a0, px, wv.x); fma2(a1, px, wv.y);
        }
        float2 r0 = up2(a0), r1 = up2(a1);
        *(float4*)(V + s*RPR + c) = make_float4(r0.x, r0.y, r1.x, r1.y);
    }
    __syncthreads();

    const int grp  = tid / 160;       // 4 head groups of 160 threads (5 warps, warp-aligned)
    const int t    = tid % 160;
    const int gbar = grp + 1;         // named barrier id (0 reserved for __syncthreads)

    // ======== per-group pipeline: groups run decoupled, only group-local bars ========
    for (int g = 0; g < 4; g++) {
        const int h = g*4 + grp;

        // ---- Q_h: thread owns 2 columns; software-pipelined Wq prefetch ----
        if (t < 150) {
            const float* wq = Wq + (size_t)h*(DD*DD) + 2*t;
            uint64_t acc[20];
            #pragma unroll
            for (int k = 0; k < 20; k++) acc[k] = 0ull;
            float2 wA = *(const float2*)(wq);
            float2 wB = *(const float2*)(wq + DD);
            #pragma unroll 1
            for (int f = 0; f < DD; f += 2) {
                int fn = (f + 2 < DD) ? (f + 2) : 0;
                float2 nA = *(const float2*)(wq + fn*DD);
                float2 nB = *(const float2*)(wq + (fn+1)*DD);
                {
                    uint64_t p0 = pk2(wA.x, wA.x), p1 = pk2(wA.y, wA.y);
                    const ulonglong2* xr = (const ulonglong2*)(xT + f*W_XP);
                    ulonglong2 x0 = xr[0], x1 = xr[1], x2 = xr[2], x3 = xr[3], x4 = xr[4];
                    fma2(acc[0], x0.x, p0);  fma2(acc[10], x0.x, p1);
                    fma2(acc[1], x0.y, p0);  fma2(acc[11], x0.y, p1);
                    fma2(acc[2], x1.x, p0);  fma2(acc[12], x1.x, p1);
                    fma2(acc[3], x1.y, p0);  fma2(acc[13], x1.y, p1);
                    fma2(acc[4], x2.x, p0);  fma2(acc[14], x2.x, p1);
                    fma2(acc[5], x2.y, p0);  fma2(acc[15], x2.y, p1);
                    fma2(acc[6], x3.x, p0);  fma2(acc[16], x3.x, p1);
                    fma2(acc[7], x3.y, p0);  fma2(acc[17], x3.y, p1);
                    fma2(acc[8], x4.x, p0);  fma2(acc[18], x4.x, p1);
                    fma2(acc[9], x4.y, p0);  fma2(acc[19], x4.y, p1);
                }
                {
                    uint64_t p0 = pk2(wB.x, wB.x), p1 = pk2(wB.y, wB.y);
                    const ulonglong2* xr = (const ulonglong2*)(xT + (f+1)*W_XP);
                    ulonglong2 x0 = xr[0], x1 = xr[1], x2 = xr[2], x3 = xr[3], x4 = xr[4];
                    fma2(acc[0], x0.x, p0);  fma2(acc[10], x0.x, p1);
                    fma2(acc[1], x0.y, p0);  fma2(acc[11], x0.y, p1);
                    fma2(acc[2], x1.x, p0);  fma2(acc[12], x1.x, p1);
                    fma2(acc[3], x1.y, p0);  fma2(acc[13], x1.y, p1);
                    fma2(acc[4], x2.x, p0);  fma2(acc[14], x2.x, p1);
                    fma2(acc[5], x2.y, p0);  fma2(acc[15], x2.y, p1);
                    fma2(acc[6], x3.x, p0);  fma2(acc[16], x3.x, p1);
                    fma2(acc[7], x3.y, p0);  fma2(acc[17], x3.y, p1);
                    fma2(acc[8], x4.x, p0);  fma2(acc[18], x4.x, p1);
                    fma2(acc[9], x4.y, p0);  fma2(acc[19], x4.y, p1);
                }
                wA = nA; wB = nB;
            }
            float* q0 = qT + grp*(300*W_QP) + (2*t)*W_QP;
            float* q1 = q0 + W_QP;
            #pragma unroll
            for (int k = 0; k < 10; k++) {
                float2 a = up2(acc[k]);    q0[2*k] = a.x; q0[2*k+1] = a.y;
                float2 b = up2(acc[10+k]); q1[2*k] = b.x; q1[2*k+1] = b.y;
            }
        }
        GBAR(gbar);

        // ---- logits (group-local): 100 jobs = 20 s x 5 u-quads ----
        if (t < 100) {
            int s = t % 20, uq = t / 20;
            const float* qh = qT + grp*(300*W_QP);
            uint64_t a0 = 0, a1 = 0;
            #pragma unroll 4
            for (int e = 0; e < DD; e++) {
                float q = qh[e*W_QP + s];
                uint64_t pq = pk2(q, q);
                ulonglong2 xv = *(const ulonglong2*)(xT + e*W_XP + uq*4);
                fma2(a0, pq, xv.x); fma2(a1, pq, xv.y);
            }
            float2 r0 = up2(a0), r1 = up2(a1);
            float* ar = attn + (grp*TT + s)*21 + uq*4;
            ar[0]=r0.x*SCALE; ar[1]=r0.y*SCALE; ar[2]=r1.x*SCALE; ar[3]=r1.y*SCALE;
        }
        GBAR(gbar);

        // ---- softmax (group-local): 20 rows ----
        if (t < 20) {
            float* row = attn + (grp*TT + t)*21;
            float m = row[0];
            #pragma unroll
            for (int u = 1; u < TT; u++) m = fmaxf(m, row[u]);
            float sum = 0.f;
            #pragma unroll
            for (int u = 0; u < TT; u++) { float e = __expf(row[u]-m); row[u]=e; sum+=e; }
            float inv = 1.f/sum;
            #pragma unroll
            for (int u = 0; u < TT; u++) row[u] *= inv;
        }
        GBAR(gbar);

        // ---- val = attn @ V (group-local): 320 jobs, 2 per thread ----
        #pragma unroll
        for (int j = 0; j < 2; j++) {
            int p = t + j*160;
            int s = p >> 4, v = p & 15;
            const float* ar = attn + (grp*TT + s)*21;
            const float* vc = V + h*VDIM + v;
            float a = 0.f;
            #pragma unroll
            for (int u = 0; u < TT; u++) a += ar[u]*vc[u*RPR];
            val[s*RPR + h*VDIM + v] = a;
        }
        GBAR(gbar);   // protects qT/attn reuse next head (group-local state)
    }
    __syncthreads();  // all groups' val complete before pooling

    // ---- additive pooling: k-quads, f32x2, MLP-8 on Wk loads ----
    if (tid < TT) wl[tid] = 0.f;
    __syncthreads();
    for (int p = tid; p < TT*50; p += 640) {
        int s = p/50, kq = p%50, k = kq*4;
        float4 b4 = *(const float4*)(bk + k);
        uint64_t a0 = pk2(b4.x, b4.y), a1 = pk2(b4.z, b4.w);
        const float* vr  = val + s*RPR;
        const float* wkp = Wk + k;
        #pragma unroll 8
        for (int r = 0; r < RPR; r++) {
            uint64_t pv = pk2(vr[r], vr[r]);
            ulonglong2 wv = *(const ulonglong2*)(wkp + r*QDQ);
            fma2(a0, pv, wv.x); fma2(a1, pv, wv.y);
        }
        float2 r0 = up2(a0), r1 = up2(a1);
        float4 q4 = *(const float4*)(qv + k);
        float ts = tanhf(r0.x)*q4.x + tanhf(r0.y)*q4.y + tanhf(r1.x)*q4.z + tanhf(r1.y)*q4.w;
        atomicAdd(&wl[s], ts);
    }
    __syncthreads();
    if (tid == 0) {
        float m = -1e30f;
        for (int s = 0; s < TT; s++) { wl[s] *= SCALE; m = fmaxf(m, wl[s]); }
        float sum = 0.f;
        for (int s = 0; s < TT; s++) { float e = __expf(wl[s]-m); wl[s]=e; sum+=e; }
        float inv = 1.f/sum;
        for (int s = 0; s < TT; s++) wl[s] *= inv;
    }
    __syncthreads();
    if (tid < RPR) {
        float a = 0.f;
        #pragma unroll
        for (int s = 0; s < TT; s++) a += wl[s] * val[s*RPR + tid];
        float* outp = (item < BB*CDDN) ? (g_cdd + item*RPR)
                                       : (g_his + (item - BB*CDDN)*RPR);
        outp[tid] = a;
    }
}

// ================= news level: (b,h)-parallel attention =================
// smem: xT[256][52] | qT[256][51] | attn[50][51] | Vh[50][16]
#define NA_XP 52
#define NA_QP 51
#define NA_QT_OFF (256*NA_XP)                 // 13312
#define NA_AT_OFF (NA_QT_OFF + 256*NA_QP)     // 26368
#define NA_V_OFF  (NA_AT_OFF + 50*51 + 2)     // 28920  (16B-aligned)
#define NA_SMEM_FLOATS (NA_V_OFF + 50*16)     // 29720 (118.9 KB)

__global__ __launch_bounds__(256, 1)
void news_attn_kernel(const float* __restrict__ Wq, const float* __restrict__ Wv)
{
    float* xT   = sm;
    float* qT   = sm + NA_QT_OFF;
    float* attn = sm + NA_AT_OFF;
    float* Vh   = sm + NA_V_OFF;

    const int tid = threadIdx.x;
    const int h   = blockIdx.x;
    const int b   = blockIdx.y;
    const float* x = g_his + b*HISN*RPR;     // [50][256]

    for (int p = tid; p < HISN*RPR; p += 256) {
        int f = p & 255, s = p >> 8;
        xT[f*NA_XP + s] = x[p];
    }
    for (int p = tid; p < 512; p += 256)       // zero pad cols 50,51
        xT[(p>>1)*NA_XP + 50 + (p&1)] = 0.f;
    __syncthreads();

    // Vh = x @ Wv_h : 50x4 quad jobs, unroll 4
    if (tid < 200) {
        int s = tid >> 2, v = (tid & 3)*4;
        const float* w = Wv + h*(RPR*VDIM) + v;
        uint64_t a0 = 0, a1 = 0;
        #pragma unroll 4
        for (int f = 0; f < RPR; f++) {
            float xv = xT[f*NA_XP + s];
            uint64_t px = pk2(xv, xv);
            ulonglong2 wv = *(const ulonglong2*)(w + f*VDIM);
            fma2(a0, px, wv.x); fma2(a1, px, wv.y);
        }
        float2 r0 = up2(a0), r1 = up2(a1);
        *(float4*)(Vh + s*16 + v) = make_float4(r0.x, r0.y, r1.x, r1.y);
    }

    // Q_h: thread = column tid, 25 s-pairs; software-pipelined Wq prefetch
    {
        uint64_t acc[25];
        #pragma unroll
        for (int k = 0; k < 25; k++) acc[k] = 0ull;
        const float* wq = Wq + (size_t)h*(RPR*RPR) + tid;
        float w0 = wq[0];
        float w1 = wq[RPR];
        #pragma unroll 1
        for (int f = 0; f < RPR; f += 2) {
            int fn = (f + 2 < RPR) ? (f + 2) : 0;
            float n0 = wq[fn*RPR];
            float n1 = wq[(fn+1)*RPR];
            {
                uint64_t pw = pk2(w0, w0);
                const ulonglong2* xr = (const ulonglong2*)(xT + f*NA_XP);
                #pragma unroll
                for (int k = 0; k < 12; k++) {
                    ulonglong2 xv = xr[k];
                    fma2(acc[2*k],   xv.x, pw);
                    fma2(acc[2*k+1], xv.y, pw);
                }
                uint64_t xt = *(const uint64_t*)(xT + f*NA_XP + 48);
                fma2(acc[24], xt, pw);
            }
            {
                uint64_t pw = pk2(w1, w1);
                const ulonglong2* xr = (const ulonglong2*)(xT + (f+1)*NA_XP);
                #pragma unroll
                for (int k = 0; k < 12; k++) {
                    ulonglong2 xv = xr[k];
                    fma2(acc[2*k],   xv.x, pw);
                    fma2(acc[2*k+1], xv.y, pw);
                }
                uint64_t xt = *(const uint64_t*)(xT + (f+1)*NA_XP + 48);
                fma2(acc[24], xt, pw);
            }
            w0 = n0; w1 = n1;
        }
        float* q0 = qT + tid*NA_QP;
        #pragma unroll
        for (int k = 0; k < 25; k++) {
            float2 a = up2(acc[k]); q0[2*k] = a.x; q0[2*k+1] = a.y;
        }
    }
    __syncthreads();

    // logits: u-quads, 50x13 jobs, unroll 4
    for (int p = tid; p < 650; p += 256) {
        int s = p % 50, uq = p / 50, u = uq*4;
        uint64_t a0 = 0, a1 = 0;
        #pragma unroll 4
        for (int e = 0; e < RPR; e++) {
            float q = qT[e*NA_QP + s];
            uint64_t pq = pk2(q, q);
            ulonglong2 xv = *(const ulonglong2*)(xT + e*NA_XP + u);
            fma2(a0, pq, xv.x); fma2(a1, pq, xv.y);
        }
        float2 r0 = up2(a0), r1 = up2(a1);
        float* ar = attn + s*51;
        ar[u] = r0.x*SCALE;
        if (u+1 < 50) ar[u+1] = r0.y*SCALE;
        if (u+2 < 50) { ar[u+2] = r1.x*SCALE; ar[u+3] = r1.y*SCALE; }
    }
    __syncthreads();

    if (tid < 50) {
        float* row = attn + tid*51;
        float m = row[0];
        for (int u = 1; u < 50; u++) m = fmaxf(m, row[u]);
        float sum = 0.f;
        for (int u = 0; u < 50; u++) { float e = __expf(row[u]-m); row[u]=e; sum+=e; }
        float inv = 1.f/sum;
        for (int u = 0; u < 50; u++) row[u] *= inv;
    }
    __syncthreads();

    for (int p = tid; p < 800; p += 256) {
        int s = p >> 4, v = p & 15;
        const float* ar = attn + s*51;
        float a = 0.f;
        #pragma unroll 10
        for (int u = 0; u < 50; u++) a += ar[u]*Vh[u*16 + v];
        g_nval[(b*HISN + s)*RPR + h*VDIM + v] = a;
    }
}

// ================= news pooling =================
#define NP_SMEM_FLOATS (HISN*RPR + HISN)      // 12850 (51.4 KB)

__global__ __launch_bounds__(256, 2)
void news_pool_kernel(const float* __restrict__ Wk, const float* __restrict__ bk,
                      const float* __restrict__ qv)
{
    float* val = sm;
    float* wl  = sm + HISN*RPR;
    const int tid = threadIdx.x;
    const int b   = blockIdx.x;

    for (int p = tid; p < HISN*RPR; p += 256) val[p] = g_nval[b*HISN*RPR + p];
    if (tid < HISN) wl[tid] = 0.f;
    __syncthreads();

    for (int p = tid; p < HISN*50; p += 256) {
        int s = p/50, kq = p%50, k = kq*4;
        float4 b4 = *(const float4*)(bk + k);
        uint64_t a0 = pk2(b4.x, b4.y), a1 = pk2(b4.z, b4.w);
        const float* vr  = val + s*RPR;
        const float* wkp = Wk + k;
        #pragma unroll 8
        for (int r = 0; r < RPR; r++) {
            uint64_t pv = pk2(vr[r], vr[r]);
            ulonglong2 wv = *(const ulonglong2*)(wkp + r*QDQ);
            fma2(a0, pv, wv.x); fma2(a1, pv, wv.y);
        }
        float2 r0 = up2(a0), r1 = up2(a1);
        float4 q4 = *(const float4*)(qv + k);
        float ts = tanhf(r0.x)*q4.x + tanhf(r0.y)*q4.y + tanhf(r1.x)*q4.z + tanhf(r1.y)*q4.w;
        atomicAdd(&wl[s], ts);
    }
    __syncthreads();
    if (tid == 0) {
        float m = -1e30f;
        for (int s = 0; s < HISN; s++) { wl[s] *= SCALE; m = fmaxf(m, wl[s]); }
        float sum = 0.f;
        for (int s = 0; s < HISN; s++) { float e = __expf(wl[s]-m); wl[s]=e; sum+=e; }
        float inv = 1.f/sum;
        for (int s = 0; s < HISN; s++) wl[s] *= inv;
    }
    __syncthreads();
    if (tid < RPR) {
        float a = 0.f;
        #pragma unroll 10
        for (int s = 0; s < HISN; s++) a += wl[s] * val[s*RPR + tid];
        g_user[b*RPR + tid] = a;
    }
}

// ================= scores + log_softmax =================
__global__ void score_kernel(float* __restrict__ out)
{
    __shared__ float sc[CDDN];
    const int b = blockIdx.x;
    const int w = threadIdx.x >> 5, lane = threadIdx.x & 31;
    if (w < CDDN) {
        const float* c = g_cdd + (b*CDDN + w)*RPR;
        const float* u = g_user + b*RPR;
        float a = 0.f;
        #pragma unroll
        for (int k = lane; k < RPR; k += 32) a += c[k]*u[k];
        #pragma unroll
        for (int off = 16; off; off >>= 1) a += __shfl_down_sync(0xffffffffu, a, off);
        if (lane == 0) sc[w] = a;
    }
    __syncthreads();
    if (threadIdx.x == 0) {
        float m = sc[0];
        for (int c = 1; c < CDDN; c++) m = fmaxf(m, sc[c]);
        float sum = 0.f;
        for (int c = 0; c < CDDN; c++) sum += __expf(sc[c]-m);
        float lse = logf(sum) + m;
        for (int c = 0; c < CDDN; c++) out[b*CDDN + c] = sc[c] - lse;
    }
}

// ================= launch =================
extern "C" void kernel_launch(void* const* d_in, const int* in_sizes, int n_in,
                              void* d_out, int out_size)
{
    (void)in_sizes; (void)n_in; (void)out_size;
    const int*   cand    = (const int*)d_in[0];
    const int*   clicked = (const int*)d_in[1];
    const float* emb     = (const float*)d_in[2];
    const float* Wq_w    = (const float*)d_in[3];
    const float* Wv_w    = (const float*)d_in[4];
    const float* Wk_w    = (const float*)d_in[5];
    const float* bk_w    = (const float*)d_in[6];
    const float* q_w     = (const float*)d_in[7];
    const float* Wq_n    = (const float*)d_in[8];
    const float* Wv_n    = (const float*)d_in[9];
    const float* Wk_n    = (const float*)d_in[10];
    const float* bk_n    = (const float*)d_in[11];
    const float* q_n     = (const float*)d_in[12];
    float* out = (float*)d_out;

    const size_t smw  = W_SMEM_FLOATS  * sizeof(float);
    const size_t smna = NA_SMEM_FLOATS * sizeof(float);
    const size_t smnp = NP_SMEM_FLOATS * sizeof(float);
    cudaFuncSetAttribute(word_kernel,      cudaFuncAttributeMaxDynamicSharedMemorySize, (int)smw);
    cudaFuncSetAttribute(news_attn_kernel, cudaFuncAttributeMaxDynamicSharedMemorySize, (int)smna);
    cudaFuncSetAttribute(news_pool_kernel, cudaFuncAttributeMaxDynamicSharedMemorySize, (int)smnp);

    word_kernel<<<NITEMS, 640, smw>>>(cand, clicked, emb, Wq_w, Wv_w, Wk_w, bk_w, q_w);
    news_attn_kernel<<<dim3(HH, BB), 256, smna>>>(Wq_n, Wv_n);
    news_pool_kernel<<<BB, 256, smnp>>>(Wk_n, bk_n, q_n);
    score_kernel<<<BB, 192>>>(out);
}

// round 12
// speedup vs baseline: 1.6755x; 1.2606x over previous
#include <cuda_runtime.h>
#include <cuda_bf16.h>
#include <math.h>
#include <stdint.h>

// ---------------- problem constants ----------------
#define BB    256
#define CDDN  5
#define HISN  50
#define TT    20
#define DD    300
#define HH    16
#define VDIM  16
#define RPR   256
#define QDQ   200
#define NITEMS (BB*(CDDN+HISN))   // 14080
#define SCALE 0.05773502691896258f

// GEMM / chunking constants
#define NCHUNK 4
#define ITEMS_PC (NITEMS/NCHUNK)        // 3520
#define ROWS_PC  (ITEMS_PC*TT)          // 70400
#define KP   320                        // padded K (300 -> 320)
#define NP5  (HH*KP)                    // 5120 padded N (16 heads x 320)

// ---------------- device scratch ----------------
__device__ float g_cdd[BB*CDDN*RPR];
__device__ float g_his[BB*HISN*RPR];
__device__ float g_nval[BB*HISN*RPR];
__device__ float g_user[BB*RPR];
__device__ __nv_bfloat16 g_xhi[(size_t)NITEMS*TT*KP];   // 180 MB
__device__ __nv_bfloat16 g_xlo[(size_t)NITEMS*TT*KP];   // 180 MB
__device__ __nv_bfloat16 g_bhi[KP*NP5];                 // 3.3 MB
__device__ __nv_bfloat16 g_blo[KP*NP5];
__device__ float g_q[(size_t)ROWS_PC*NP5];              // 1.44 GB (per chunk)

// ---------------- packed f32x2 helpers ----------------
__device__ __forceinline__ uint64_t pk2(float a, float b){
    uint64_t r; asm("mov.b64 %0,{%1,%2};" : "=l"(r) : "f"(a), "f"(b)); return r;
}
__device__ __forceinline__ void fma2(uint64_t& d, uint64_t a, uint64_t b){
    asm("fma.rn.f32x2 %0,%1,%2,%0;" : "+l"(d) : "l"(a), "l"(b));
}
__device__ __forceinline__ float2 up2(uint64_t v){
    float2 f; asm("mov.b64 {%0,%1},%2;" : "=f"(f.x), "=f"(f.y) : "l"(v)); return f;
}
#define GBAR(id) asm volatile("bar.sync %0, 160;" :: "r"(id) : "memory")

__device__ __forceinline__ uint32_t s2u(const void* p){
    return (uint32_t)__cvta_generic_to_shared(p);
}
__device__ __forceinline__ void ldmx4(uint32_t* r, uint32_t addr){
    asm volatile("ldmatrix.sync.aligned.m8n8.x4.shared.b16 {%0,%1,%2,%3},[%4];"
        : "=r"(r[0]),"=r"(r[1]),"=r"(r[2]),"=r"(r[3]) : "r"(addr));
}
__device__ __forceinline__ void ldmx2t(uint32_t* r, uint32_t addr){
    asm volatile("ldmatrix.sync.aligned.m8n8.x2.trans.shared.b16 {%0,%1},[%2];"
        : "=r"(r[0]),"=r"(r[1]) : "r"(addr));
}
__device__ __forceinline__ void mma16816(float* c, const uint32_t* a, const uint32_t* b){
    asm volatile("mma.sync.aligned.m16n8k16.row.col.f32.bf16.bf16.f32 "
        "{%0,%1,%2,%3},{%4,%5,%6,%7},{%8,%9},{%0,%1,%2,%3};"
        : "+f"(c[0]),"+f"(c[1]),"+f"(c[2]),"+f"(c[3])
        : "r"(a[0]),"r"(a[1]),"r"(a[2]),"r"(a[3]),"r"(b[0]),"r"(b[1]));
}

extern __shared__ float sm[];

// ================= weight conversion: Wq -> bf16 hi/lo B matrix [KP][NP5] =================
__global__ void conv_w_kernel(const float* __restrict__ Wq)
{
    int idx = blockIdx.x*256 + threadIdx.x;
    if (idx >= KP*NP5) return;
    int k = idx / NP5, n = idx % NP5;
    int h = n / KP, e = n % KP;
    float v = 0.f;
    if (k < DD && e < DD) v = Wq[h*DD*DD + k*DD + e];
    __nv_bfloat16 hi = __float2bfloat16(v);
    g_bhi[idx] = hi;
    g_blo[idx] = __float2bfloat16(v - __bfloat162float(hi));
}

// ================= x gather + bf16 split: [NITEMS*20][KP] =================
__global__ void conv_x_kernel(const int* __restrict__ cand, const int* __restrict__ clicked,
                              const float* __restrict__ emb)
{
    __shared__ int tok[TT];
    const int item = blockIdx.x, tid = threadIdx.x;
    if (tid < TT) {
        const int* tp = (item < BB*CDDN) ? (cand + item*TT)
                                         : (clicked + (item - BB*CDDN)*TT);
        tok[tid] = tp[tid];
    }
    __syncthreads();
    size_t base = (size_t)item*TT*KP;
    for (int p = tid; p < TT*KP; p += 256) {
        int s = p / KP, k = p % KP;
        float v = (k < DD) ? emb[(size_t)tok[s]*DD + k] : 0.f;
        __nv_bfloat16 hi = __float2bfloat16(v);
        g_xhi[base + p] = hi;
        g_xlo[base + p] = __float2bfloat16(v - __bfloat162float(hi));
    }
}

// ================= Q GEMM: [128 x 128] tiles, bf16-split mma.sync =================
#define PA 40     // A smem pitch (bf16)
#define PB 136    // B smem pitch (bf16)

__global__ __launch_bounds__(512, 1)
void qgemm_kernel(int row_off)
{
    __shared__ __nv_bfloat16 Ah[128*PA], Al[128*PA];
    __shared__ __nv_bfloat16 Bh[32*PB],  Bl[32*PB];

    const int tid  = threadIdx.x;
    const int nb   = blockIdx.x;   // 0..39
    const int mb   = blockIdx.y;   // 0..549
    const size_t arow = (size_t)row_off + (size_t)mb*128;

    // loader mapping
    const int la_r = tid >> 2, la_s = (tid & 3)*8;      // A: 128 rows x 4 segs
    const int lb_r = tid >> 4, lb_s = (tid & 15)*8;     // B: 32 rows x 16 segs
    const __nv_bfloat16* pAh = g_xhi + (arow + la_r)*KP + la_s;
    const __nv_bfloat16* pAl = g_xlo + (arow + la_r)*KP + la_s;
    const __nv_bfloat16* pBh = g_bhi + (size_t)lb_r*NP5 + nb*128 + lb_s;
    const __nv_bfloat16* pBl = g_blo + (size_t)lb_r*NP5 + nb*128 + lb_s;

    uint4 rah = *(const uint4*)(pAh);
    uint4 ral = *(const uint4*)(pAl);
    uint4 rbh = *(const uint4*)(pBh);
    uint4 rbl = *(const uint4*)(pBl);
    *(uint4*)(Ah + la_r*PA + la_s) = rah;
    *(uint4*)(Al + la_r*PA + la_s) = ral;
    *(uint4*)(Bh + lb_r*PB + lb_s) = rbh;
    *(uint4*)(Bl + lb_r*PB + lb_s) = rbl;
    __syncthreads();

    const int warp = tid >> 5, lane = tid & 31;
    const int wm = warp >> 2, wn = warp & 3;

    float c[2][4][4];
    #pragma unroll
    for (int mt = 0; mt < 2; mt++)
        #pragma unroll
        for (int ns = 0; ns < 4; ns++)
            #pragma unroll
            for (int i = 0; i < 4; i++) c[mt][ns][i] = 0.f;

    // ldmatrix base addresses
    const uint32_t aAh = s2u(Ah) + (uint32_t)(((wm*32 + (lane & 15))*PA + (lane >> 4)*8) * 2);
    const uint32_t aAl = s2u(Al) + (uint32_t)(((wm*32 + (lane & 15))*PA + (lane >> 4)*8) * 2);
    const uint32_t aBh = s2u(Bh) + (uint32_t)(((lane & 15)*PB + wn*32) * 2);
    const uint32_t aBl = s2u(Bl) + (uint32_t)(((lane & 15)*PB + wn*32) * 2);

    #pragma unroll 1
    for (int ck = 0; ck < 10; ck++) {
        if (ck < 9) {   // prefetch next chunk into registers (overlaps compute)
            rah = *(const uint4*)(pAh + (ck+1)*32);
            ral = *(const uint4*)(pAl + (ck+1)*32);
            rbh = *(const uint4*)(pBh + (size_t)(ck+1)*32*NP5);
            rbl = *(const uint4*)(pBl + (size_t)(ck+1)*32*NP5);
        }
        #pragma unroll
        for (int k16 = 0; k16 < 2; k16++) {
            uint32_t ah[2][4], al[2][4], bh[4][2], bl[4][2];
            #pragma unroll
            for (int mt = 0; mt < 2; mt++) {
                ldmx4(ah[mt], aAh + mt*16*PA*2 + k16*32);
                ldmx4(al[mt], aAl + mt*16*PA*2 + k16*32);
            }
            #pragma unroll
            for (int ns = 0; ns < 4; ns++) {
                ldmx2t(bh[ns], aBh + ns*16 + k16*16*PB*2);
                ldmx2t(bl[ns], aBl + ns*16 + k16*16*PB*2);
            }
            #pragma unroll
            for (int mt = 0; mt < 2; mt++)
                #pragma unroll
                for (int ns = 0; ns < 4; ns++) {
                    mma16816(c[mt][ns], ah[mt], bh[ns]);
                    mma16816(c[mt][ns], ah[mt], bl[ns]);
                    mma16816(c[mt][ns], al[mt], bh[ns]);
                }
        }
        __syncthreads();
        if (ck < 9) {
            *(uint4*)(Ah + la_r*PA + la_s) = rah;
            *(uint4*)(Al + la_r*PA + la_s) = ral;
            *(uint4*)(Bh + lb_r*PB + lb_s) = rbh;
            *(uint4*)(Bl + lb_r*PB + lb_s) = rbl;
        }
        __syncthreads();
    }

    // epilogue: C -> g_q (chunk-local rows)
    const int orow0 = mb*128 + wm*32;
    #pragma unroll
    for (int mt = 0; mt < 2; mt++)
        #pragma unroll
        for (int ns = 0; ns < 4; ns++) {
            int r   = orow0 + mt*16 + (lane >> 2);
            int col = nb*128 + wn*32 + ns*8 + (lane & 3)*2;
            *(float2*)(g_q + (size_t)r*NP5 + col)     = make_float2(c[mt][ns][0], c[mt][ns][1]);
            *(float2*)(g_q + (size_t)(r+8)*NP5 + col) = make_float2(c[mt][ns][2], c[mt][ns][3]);
        }
}

// ================= word-level encoder (Q read from g_q) =================
#define W_XP 24
#define W_QP 21
#define W_QT_OFF  (300*W_XP)
#define W_V_OFF   (W_QT_OFF + 4*300*W_QP)
#define W_VAL_OFF (W_V_OFF  + TT*RPR)
#define W_ATT_OFF (W_VAL_OFF + TT*RPR)
#define W_WL_OFF  (W_ATT_OFF + 4*TT*21)
#define W_SMEM_FLOATS (W_WL_OFF + TT)        // 44340 (177.4 KB)

__global__ __launch_bounds__(640, 1)
void word_kernel(int item_off,
                 const int* __restrict__ cand, const int* __restrict__ clicked,
                 const float* __restrict__ emb,
                 const float* __restrict__ Wv,
                 const float* __restrict__ Wk, const float* __restrict__ bk,
                 const float* __restrict__ qv)
{
    float* xT   = sm;
    float* qT   = sm + W_QT_OFF;
    float* V    = sm + W_V_OFF;
    float* val  = sm + W_VAL_OFF;
    float* attn = sm + W_ATT_OFF;
    float* wl   = sm + W_WL_OFF;
    __shared__ int tok[TT];

    const int tid   = threadIdx.x;
    const int lit   = blockIdx.x;          // chunk-local item
    const int item  = item_off + lit;      // global item

    const int* tp = (item < BB*CDDN) ? (cand + item*TT)
                                     : (clicked + (item - BB*CDDN)*TT);
    if (tid < TT) tok[tid] = tp[tid];
    __syncthreads();

    for (int p = tid; p < TT*DD; p += 640) {
        int s = p / DD, f = p - s*DD;
        xT[f*W_XP + s] = emb[tok[s]*DD + f];
    }
    __syncthreads();

    // ---- V = x @ Wv_all ----
    for (int p = tid; p < TT*64; p += 640) {
        int s = p >> 6, cq = p & 63, cc = cq*4;
        int h = cc >> 4, v = cc & 15;
        const float* w = Wv + h*(DD*VDIM) + v;
        uint64_t a0 = 0, a1 = 0;
        #pragma unroll 4
        for (int f = 0; f < DD; f++) {
            float xv = xT[f*W_XP + s];
            uint64_t px = pk2(xv, xv);
            ulonglong2 wv = *(const ulonglong2*)(w + f*VDIM);
            fma2(a0, px, wv.x); fma2(a1, px, wv.y);
        }
        float2 r0 = up2(a0), r1 = up2(a1);
        *(float4*)(V + s*RPR + cc) = make_float4(r0.x, r0.y, r1.x, r1.y);
    }
    __syncthreads();

    const int grp  = tid / 160;
    const int t    = tid % 160;
    const int gbar = grp + 1;

    for (int g = 0; g < 4; g++) {
        const int h = g*4 + grp;

        // ---- load Q_h tile from g_q into qT plane (transposed) ----
        {
            const float* qsrc = g_q + (size_t)(lit*TT)*NP5 + h*KP;
            float* qp = qT + grp*(300*W_QP);
            for (int j = t; j < 1500; j += 160) {
                int s = j / 75, c4 = j % 75, e = c4*4;
                float4 q4 = *(const float4*)(qsrc + (size_t)s*NP5 + e);
                qp[(e+0)*W_QP + s] = q4.x;
                qp[(e+1)*W_QP + s] = q4.y;
                qp[(e+2)*W_QP + s] = q4.z;
                qp[(e+3)*W_QP + s] = q4.w;
            }
        }
        GBAR(gbar);

        // ---- logits ----
        if (t < 100) {
            int s = t % 20, uq = t / 20;
            const float* qh = qT + grp*(300*W_QP);
            uint64_t a0 = 0, a1 = 0;
            #pragma unroll 4
            for (int e = 0; e < DD; e++) {
                float q = qh[e*W_QP + s];
                uint64_t pq = pk2(q, q);
                ulonglong2 xv = *(const ulonglong2*)(xT + e*W_XP + uq*4);
                fma2(a0, pq, xv.x); fma2(a1, pq, xv.y);
            }
            float2 r0 = up2(a0), r1 = up2(a1);
            float* ar = attn + (grp*TT + s)*21 + uq*4;
            ar[0]=r0.x*SCALE; ar[1]=r0.y*SCALE; ar[2]=r1.x*SCALE; ar[3]=r1.y*SCALE;
        }
        GBAR(gbar);

        // ---- softmax ----
        if (t < 20) {
            float* row = attn + (grp*TT + t)*21;
            float m = row[0];
            #pragma unroll
            for (int u = 1; u < TT; u++) m = fmaxf(m, row[u]);
            float sum = 0.f;
            #pragma unroll
            for (int u = 0; u < TT; u++) { float e = __expf(row[u]-m); row[u]=e; sum+=e; }
            float inv = 1.f/sum;
            #pragma unroll
            for (int u = 0; u < TT; u++) row[u] *= inv;
        }
        GBAR(gbar);

        // ---- val = attn @ V ----
        #pragma unroll
        for (int j = 0; j < 2; j++) {
            int p = t + j*160;
            int s = p >> 4, v = p & 15;
            const float* ar = attn + (grp*TT + s)*21;
            const float* vc = V + h*VDIM + v;
            float a = 0.f;
            #pragma unroll
            for (int u = 0; u < TT; u++) a += ar[u]*vc[u*RPR];
            val[s*RPR + h*VDIM + v] = a;
        }
        GBAR(gbar);
    }
    __syncthreads();

    // ---- additive pooling ----
    if (tid < TT) wl[tid] = 0.f;
    __syncthreads();
    for (int p = tid; p < TT*50; p += 640) {
        int s = p/50, kq = p%50, k = kq*4;
        float4 b4 = *(const float4*)(bk + k);
        uint64_t a0 = pk2(b4.x, b4.y), a1 = pk2(b4.z, b4.w);
        const float* vr  = val + s*RPR;
        const float* wkp = Wk + k;
        #pragma unroll 8
        for (int r = 0; r < RPR; r++) {
            uint64_t pv = pk2(vr[r], vr[r]);
            ulonglong2 wv = *(const ulonglong2*)(wkp + r*QDQ);
            fma2(a0, pv, wv.x); fma2(a1, pv, wv.y);
        }
        float2 r0 = up2(a0), r1 = up2(a1);
        float4 q4 = *(const float4*)(qv + k);
        float ts = tanhf(r0.x)*q4.x + tanhf(r0.y)*q4.y + tanhf(r1.x)*q4.z + tanhf(r1.y)*q4.w;
        atomicAdd(&wl[s], ts);
    }
    __syncthreads();
    if (tid == 0) {
        float m = -1e30f;
        for (int s = 0; s < TT; s++) { wl[s] *= SCALE; m = fmaxf(m, wl[s]); }
        float sum = 0.f;
        for (int s = 0; s < TT; s++) { float e = __expf(wl[s]-m); wl[s]=e; sum+=e; }
        float inv = 1.f/sum;
        for (int s = 0; s < TT; s++) wl[s] *= inv;
    }
    __syncthreads();
    if (tid < RPR) {
        float a = 0.f;
        #pragma unroll
        for (int s = 0; s < TT; s++) a += wl[s] * val[s*RPR + tid];
        float* outp = (item < BB*CDDN) ? (g_cdd + item*RPR)
                                       : (g_his + (item - BB*CDDN)*RPR);
        outp[tid] = a;
    }
}

// ================= news level (unchanged) =================
#define NA_XP 52
#define NA_QP 51
#define NA_QT_OFF (256*NA_XP)
#define NA_AT_OFF (NA_QT_OFF + 256*NA_QP)
#define NA_V_OFF  (NA_AT_OFF + 50*51 + 2)
#define NA_SMEM_FLOATS (NA_V_OFF + 50*16)

__global__ __launch_bounds__(256, 1)
void news_attn_kernel(const float* __restrict__ Wq, const float* __restrict__ Wv)
{
    float* xT   = sm;
    float* qT   = sm + NA_QT_OFF;
    float* attn = sm + NA_AT_OFF;
    float* Vh   = sm + NA_V_OFF;

    const int tid = threadIdx.x;
    const int h   = blockIdx.x;
    const int b   = blockIdx.y;
    const float* x = g_his + b*HISN*RPR;

    for (int p = tid; p < HISN*RPR; p += 256) {
        int f = p & 255, s = p >> 8;
        xT[f*NA_XP + s] = x[p];
    }
    for (int p = tid; p < 512; p += 256)
        xT[(p>>1)*NA_XP + 50 + (p&1)] = 0.f;
    __syncthreads();

    if (tid < 200) {
        int s = tid >> 2, v = (tid & 3)*4;
        const float* w = Wv + h*(RPR*VDIM) + v;
        uint64_t a0 = 0, a1 = 0;
        #pragma unroll 4
        for (int f = 0; f < RPR; f++) {
            float xv = xT[f*NA_XP + s];
            uint64_t px = pk2(xv, xv);
            ulonglong2 wv = *(const ulonglong2*)(w + f*VDIM);
            fma2(a0, px, wv.x); fma2(a1, px, wv.y);
        }
        float2 r0 = up2(a0), r1 = up2(a1);
        *(float4*)(Vh + s*16 + v) = make_float4(r0.x, r0.y, r1.x, r1.y);
    }

    {
        uint64_t acc[25];
        #pragma unroll
        for (int k = 0; k < 25; k++) acc[k] = 0ull;
        const float* wq = Wq + (size_t)h*(RPR*RPR) + tid;
        float w0 = wq[0];
        float w1 = wq[RPR];
        #pragma unroll 1
        for (int f = 0; f < RPR; f += 2) {
            int fn = (f + 2 < RPR) ? (f + 2) : 0;
            float n0 = wq[fn*RPR];
            float n1 = wq[(fn+1)*RPR];
            {
                uint64_t pw = pk2(w0, w0);
                const ulonglong2* xr = (const ulonglong2*)(xT + f*NA_XP);
                #pragma unroll
                for (int k = 0; k < 12; k++) {
                    ulonglong2 xv = xr[k];
                    fma2(acc[2*k],   xv.x, pw);
                    fma2(acc[2*k+1], xv.y, pw);
                }
                uint64_t xt = *(const uint64_t*)(xT + f*NA_XP + 48);
                fma2(acc[24], xt, pw);
            }
            {
                uint64_t pw = pk2(w1, w1);
                const ulonglong2* xr = (const ulonglong2*)(xT + (f+1)*NA_XP);
                #pragma unroll
                for (int k = 0; k < 12; k++) {
                    ulonglong2 xv = xr[k];
                    fma2(acc[2*k],   xv.x, pw);
                    fma2(acc[2*k+1], xv.y, pw);
                }
                uint64_t xt = *(const uint64_t*)(xT + (f+1)*NA_XP + 48);
                fma2(acc[24], xt, pw);
            }
            w0 = n0; w1 = n1;
        }
        float* q0 = qT + tid*NA_QP;
        #pragma unroll
        for (int k = 0; k < 25; k++) {
            float2 a = up2(acc[k]); q0[2*k] = a.x; q0[2*k+1] = a.y;
        }
    }
    __syncthreads();

    for (int p = tid; p < 650; p += 256) {
        int s = p % 50, uq = p / 50, u = uq*4;
        uint64_t a0 = 0, a1 = 0;
        #pragma unroll 4
        for (int e = 0; e < RPR; e++) {
            float q = qT[e*NA_QP + s];
            uint64_t pq = pk2(q, q);
            ulonglong2 xv = *(const ulonglong2*)(xT + e*NA_XP + u);
            fma2(a0, pq, xv.x); fma2(a1, pq, xv.y);
        }
        float2 r0 = up2(a0), r1 = up2(a1);
        float* ar = attn + s*51;
        ar[u] = r0.x*SCALE;
        if (u+1 < 50) ar[u+1] = r0.y*SCALE;
        if (u+2 < 50) { ar[u+2] = r1.x*SCALE; ar[u+3] = r1.y*SCALE; }
    }
    __syncthreads();

    if (tid < 50) {
        float* row = attn + tid*51;
        float m = row[0];
        for (int u = 1; u < 50; u++) m = fmaxf(m, row[u]);
        float sum = 0.f;
        for (int u = 0; u < 50; u++) { float e = __expf(row[u]-m); row[u]=e; sum+=e; }
        float inv = 1.f/sum;
        for (int u = 0; u < 50; u++) row[u] *= inv;
    }
    __syncthreads();

    for (int p = tid; p < 800; p += 256) {
        int s = p >> 4, v = p & 15;
        const float* ar = attn + s*51;
        float a = 0.f;
        #pragma unroll 10
        for (int u = 0; u < 50; u++) a += ar[u]*Vh[u*16 + v];
        g_nval[(b*HISN + s)*RPR + h*VDIM + v] = a;
    }
}

#define NP_SMEM_FLOATS (HISN*RPR + HISN)

__global__ __launch_bounds__(256, 2)
void news_pool_kernel(const float* __restrict__ Wk, const float* __restrict__ bk,
                      const float* __restrict__ qv)
{
    float* val = sm;
    float* wl  = sm + HISN*RPR;
    const int tid = threadIdx.x;
    const int b   = blockIdx.x;

    for (int p = tid; p < HISN*RPR; p += 256) val[p] = g_nval[b*HISN*RPR + p];
    if (tid < HISN) wl[tid] = 0.f;
    __syncthreads();

    for (int p = tid; p < HISN*50; p += 256) {
        int s = p/50, kq = p%50, k = kq*4;
        float4 b4 = *(const float4*)(bk + k);
        uint64_t a0 = pk2(b4.x, b4.y), a1 = pk2(b4.z, b4.w);
        const float* vr  = val + s*RPR;
        const float* wkp = Wk + k;
        #pragma unroll 8
        for (int r = 0; r < RPR; r++) {
            uint64_t pv = pk2(vr[r], vr[r]);
            ulonglong2 wv = *(const ulonglong2*)(wkp + r*QDQ);
            fma2(a0, pv, wv.x); fma2(a1, pv, wv.y);
        }
        float2 r0 = up2(a0), r1 = up2(a1);
        float4 q4 = *(const float4*)(qv + k);
        float ts = tanhf(r0.x)*q4.x + tanhf(r0.y)*q4.y + tanhf(r1.x)*q4.z + tanhf(r1.y)*q4.w;
        atomicAdd(&wl[s], ts);
    }
    __syncthreads();
    if (tid == 0) {
        float m = -1e30f;
        for (int s = 0; s < HISN; s++) { wl[s] *= SCALE; m = fmaxf(m, wl[s]); }
        float sum = 0.f;
        for (int s = 0; s < HISN; s++) { float e = __expf(wl[s]-m); wl[s]=e; sum+=e; }
        float inv = 1.f/sum;
        for (int s = 0; s < HISN; s++) wl[s] *= inv;
    }
    __syncthreads();
    if (tid < RPR) {
        float a = 0.f;
        #pragma unroll 10
        for (int s = 0; s < HISN; s++) a += wl[s] * val[s*RPR + tid];
        g_user[b*RPR + tid] = a;
    }
}

__global__ void score_kernel(float* __restrict__ out)
{
    __shared__ float sc[CDDN];
    const int b = blockIdx.x;
    const int w = threadIdx.x >> 5, lane = threadIdx.x & 31;
    if (w < CDDN) {
        const float* c = g_cdd + (b*CDDN + w)*RPR;
        const float* u = g_user + b*RPR;
        float a = 0.f;
        #pragma unroll
        for (int k = lane; k < RPR; k += 32) a += c[k]*u[k];
        #pragma unroll
        for (int off = 16; off; off >>= 1) a += __shfl_down_sync(0xffffffffu, a, off);
        if (lane == 0) sc[w] = a;
    }
    __syncthreads();
    if (threadIdx.x == 0) {
        float m = sc[0];
        for (int c = 1; c < CDDN; c++) m = fmaxf(m, sc[c]);
        float sum = 0.f;
        for (int c = 0; c < CDDN; c++) sum += __expf(sc[c]-m);
        float lse = logf(sum) + m;
        for (int c = 0; c < CDDN; c++) out[b*CDDN + c] = sc[c] - lse;
    }
}

// ================= launch =================
extern "C" void kernel_launch(void* const* d_in, const int* in_sizes, int n_in,
                              void* d_out, int out_size)
{
    (void)in_sizes; (void)n_in; (void)out_size;
    const int*   cand    = (const int*)d_in[0];
    const int*   clicked = (const int*)d_in[1];
    const float* emb     = (const float*)d_in[2];
    const float* Wq_w    = (const float*)d_in[3];
    const float* Wv_w    = (const float*)d_in[4];
    const float* Wk_w    = (const float*)d_in[5];
    const float* bk_w    = (const float*)d_in[6];
    const float* q_w     = (const float*)d_in[7];
    const float* Wq_n    = (const float*)d_in[8];
    const float* Wv_n    = (const float*)d_in[9];
    const float* Wk_n    = (const float*)d_in[10];
    const float* bk_n    = (const float*)d_in[11];
    const float* q_n     = (const float*)d_in[12];
    float* out = (float*)d_out;

    const size_t smw  = W_SMEM_FLOATS  * sizeof(float);
    const size_t smna = NA_SMEM_FLOATS * sizeof(float);
    const size_t smnp = NP_SMEM_FLOATS * sizeof(float);
    cudaFuncSetAttribute(word_kernel,      cudaFuncAttributeMaxDynamicSharedMemorySize, (int)smw);
    cudaFuncSetAttribute(news_attn_kernel, cudaFuncAttributeMaxDynamicSharedMemorySize, (int)smna);
    cudaFuncSetAttribute(news_pool_kernel, cudaFuncAttributeMaxDynamicSharedMemorySize, (int)smnp);

    conv_w_kernel<<<(KP*NP5 + 255)/256, 256>>>(Wq_w);
    conv_x_kernel<<<NITEMS, 256>>>(cand, clicked, emb);

    for (int ch = 0; ch < NCHUNK; ch++) {
        qgemm_kernel<<<dim3(NP5/128, ROWS_PC/128), 512>>>(ch*ROWS_PC);
        word_kernel<<<ITEMS_PC, 640, smw>>>(ch*ITEMS_PC, cand, clicked, emb,
                                            Wv_w, Wk_w, bk_w, q_w);
    }

    news_attn_kernel<<<dim3(HH, BB), 256, smna>>>(Wq_n, Wv_n);
    news_pool_kernel<<<BB, 256, smnp>>>(Wk_n, bk_n, q_n);
    score_kernel<<<BB, 192>>>(out);
}